// round 9
// baseline (speedup 1.0000x reference)
#include <cuda_runtime.h>
#include <cuda_bf16.h>
#include <cstdint>

#define T_DIM 8192
#define O_DIM 4096
#define I_DIM 4096
#define GROUPS 16   // I_DIM / 256

// ---- scratch (allocation-free rule: __device__ globals) ----
__device__ __align__(128) int8_t g_A[(size_t)T_DIM * I_DIM];  // 32 MB: q per token (s8)
__device__ __align__(128) int8_t g_B[(size_t)O_DIM * I_DIM];  // 16 MB: w - zero (s8)
__device__ float g_sx[T_DIM];     // per-token scale
__device__ float g_zp[T_DIM];     // per-token zero point
__device__ float g_corr[O_DIM];   // sum_g s_g * sum_{i in g} (w - zero)

// ============================================================
// Kernel 1: per-token asymmetric int8 quant -> q (s8), sx, zp
// ============================================================
__global__ void quant_kernel(const float* __restrict__ x) {
    const int row = blockIdx.x;
    const int tid = threadIdx.x;
    const float4* xr = reinterpret_cast<const float4*>(x + (size_t)row * I_DIM);

    float4 v[4];
    float mn = 0.0f, mx = 0.0f;   // reference folds 0 into min/max
#pragma unroll
    for (int j = 0; j < 4; ++j) {
        v[j] = xr[tid + j * 256];
        mn = fminf(mn, fminf(fminf(v[j].x, v[j].y), fminf(v[j].z, v[j].w)));
        mx = fmaxf(mx, fmaxf(fmaxf(v[j].x, v[j].y), fmaxf(v[j].z, v[j].w)));
    }
#pragma unroll
    for (int o = 16; o > 0; o >>= 1) {
        mn = fminf(mn, __shfl_xor_sync(0xffffffffu, mn, o));
        mx = fmaxf(mx, __shfl_xor_sync(0xffffffffu, mx, o));
    }
    __shared__ float smn[8], smx[8];
    if ((tid & 31) == 0) { smn[tid >> 5] = mn; smx[tid >> 5] = mx; }
    __syncthreads();
    mn = smn[0]; mx = smx[0];
#pragma unroll
    for (int w = 1; w < 8; ++w) { mn = fminf(mn, smn[w]); mx = fmaxf(mx, smx[w]); }

    const float scale = fmaxf(__fdiv_rn(mx - mn, 255.0f), 1.1920929e-07f);
    const float dmin = __fdiv_rn(mn, scale);
    const float dmax = __fdiv_rn(mx, scale);
    float zp = ((-128.0f + dmin) + (127.0f + dmax) > 0.0f) ? (-128.0f - dmin)
                                                           : (127.0f - dmax);
    zp = rintf(fminf(fmaxf(zp, -128.0f), 127.0f));

    if (tid == 0) { g_sx[row] = scale; g_zp[row] = zp; }

    unsigned* Ar = reinterpret_cast<unsigned*>(g_A + (size_t)row * I_DIM);
#pragma unroll
    for (int j = 0; j < 4; ++j) {
        float e[4] = {v[j].x, v[j].y, v[j].z, v[j].w};
        unsigned pack = 0;
#pragma unroll
        for (int c = 0; c < 4; ++c) {
            float q = rintf(__fdiv_rn(e[c], scale)) + zp;
            q = fminf(fmaxf(q, -128.0f), 127.0f);
            int qi = (int)q;                         // exact integer in [-128,127]
            pack |= ((unsigned)(qi & 0xff)) << (c * 8);
        }
        Ar[tid + j * 256] = pack;
    }
}

// ============================================================
// Kernel 2: weight prep  b = w - zero[o,g] (s8)  +  corr_o
//   one block per output row o; thread t covers elems [t*16, t*16+16)
// ============================================================
__global__ void wprep_kernel(const int* __restrict__ w,
                             const float* __restrict__ scales,
                             const float* __restrict__ zeros) {
    const int o = blockIdx.x;
    const int t = threadIdx.x;
    const int g = t >> 4;                         // group of this thread's chunk
    const int4* wr = reinterpret_cast<const int4*>(w + (size_t)o * I_DIM);
    const int zi = __float2int_rn(zeros[o * GROUPS + g]);   // integer-valued

    int sum = 0;
    unsigned pk[4];
#pragma unroll
    for (int j = 0; j < 4; ++j) {
        int4 v = wr[t * 4 + j];
        int b0 = v.x - zi, b1 = v.y - zi, b2 = v.z - zi, b3 = v.w - zi;
        sum += b0 + b1 + b2 + b3;
        pk[j] = ((unsigned)(b0 & 0xff)) | ((unsigned)(b1 & 0xff) << 8) |
                ((unsigned)(b2 & 0xff) << 16) | ((unsigned)(b3 & 0xff) << 24);
    }
    *reinterpret_cast<uint4*>(g_B + (size_t)o * I_DIM + t * 16) =
        make_uint4(pk[0], pk[1], pk[2], pk[3]);

    // reduce over the 16 threads of each group (half-warp)
#pragma unroll
    for (int off = 8; off > 0; off >>= 1)
        sum += __shfl_down_sync(0xffffffffu, sum, off, 16);
    __shared__ float s_corr[16];
    if ((t & 15) == 0)
        s_corr[g] = (float)sum * __ldg(&scales[o * GROUPS + g]);
    __syncthreads();
    if (t == 0) {
        float c = 0.f;
#pragma unroll
        for (int gg = 0; gg < GROUPS; ++gg) c += s_corr[gg];
        g_corr[o] = c;
    }
}

// ============================================================
// Kernel 3: group-scaled int8 GEMM (mma.sync m16n8k32 + ldmatrix)
//   CTA 128x128, stage K=128 (128B rows), 4-stage cp.async ring,
//   16 warps (32x32 each). s32 group partials (exact), folded by
//   scale[o,g]; zp-correction + scale_x at the epilogue.
// ============================================================
#define BKB 128                 // bytes per smem row (128 s8 K-values)
#define NSTG 4
#define STGB (128 * BKB)        // 16 KB per operand stage
#define NKB (I_DIM / 128)       // 32 k-blocks, 2 per group

__device__ __forceinline__ void cp_async16(uint32_t smem, const void* gmem) {
    asm volatile("cp.async.cg.shared.global [%0], [%1], 16;\n" :: "r"(smem), "l"(gmem));
}
__device__ __forceinline__ void cp_commit() { asm volatile("cp.async.commit_group;\n"); }
__device__ __forceinline__ void cp_wait2()  { asm volatile("cp.async.wait_group 2;\n"); }

__device__ __forceinline__ void ldmx4(unsigned& r0, unsigned& r1, unsigned& r2, unsigned& r3,
                                      uint32_t addr) {
    asm volatile("ldmatrix.sync.aligned.m8n8.x4.shared.b16 {%0,%1,%2,%3}, [%4];"
                 : "=r"(r0), "=r"(r1), "=r"(r2), "=r"(r3) : "r"(addr));
}

__global__ void __launch_bounds__(512, 1)
gemm_kernel(const float* __restrict__ scales, float* __restrict__ out) {
    extern __shared__ char smem_dyn[];
    uint32_t raw = (uint32_t)__cvta_generic_to_shared(smem_dyn);
    const uint32_t sA = (raw + 127u) & ~127u;            // 128B-aligned rows
    const uint32_t sB = sA + NSTG * STGB;
    float* s_sc = reinterpret_cast<float*>(smem_dyn + (sB + NSTG * STGB - raw));

    const int tid  = threadIdx.x;
    const int wid  = tid >> 5;
    const int lane = tid & 31;
    const int bm   = blockIdx.y * 128;
    const int bn   = blockIdx.x * 128;

    // warp grid 4(M) x 4(N); warp tile 32x32
    const int mbase = (wid & 3) * 32;
    const int nbase = (wid >> 2) * 32;
    const int q  = lane >> 3;          // ldmatrix address quad
    const int l7 = lane & 7;

    // --- producer indexing: each thread loads rows r0, r0+64, chunk j ---
    const int r0 = tid >> 3;           // 0..63
    const int j  = tid & 7;
    const uint32_t swoff = (uint32_t)((j ^ (r0 & 7)) << 4);
    const uint32_t dA0 = sA + r0 * BKB + swoff;
    const uint32_t dA1 = dA0 + 64 * BKB;
    const uint32_t dB0 = sB + r0 * BKB + swoff;
    const uint32_t dB1 = dB0 + 64 * BKB;
    const char* Ar0 = (const char*)g_A + (size_t)(bm + r0) * I_DIM + j * 16;
    const char* Ar1 = Ar0 + (size_t)64 * I_DIM;
    const char* Br0 = (const char*)g_B + (size_t)(bn + r0) * I_DIM + j * 16;
    const char* Br1 = Br0 + (size_t)64 * I_DIM;

    // --- ldmatrix per-lane row constants (b16 view: 16B chunk = 16 s8 K) ---
    uint32_t arow128[2], arow7[2], brow128[2], brow7[2];
#pragma unroll
    for (int mi = 0; mi < 2; ++mi) {
        int r = mbase + mi * 16 + (q & 1) * 8 + l7;
        arow128[mi] = (uint32_t)(r * BKB);
        arow7[mi]   = (uint32_t)(r & 7);
    }
#pragma unroll
    for (int p = 0; p < 2; ++p) {
        int r = nbase + p * 16 + (q >> 1) * 8 + l7;
        brow128[p] = (uint32_t)(r * BKB);
        brow7[p]   = (uint32_t)(r & 7);
    }
    const uint32_t aq = (uint32_t)(q >> 1);   // A k-chunk offset (16B units)
    const uint32_t bq = (uint32_t)(q & 1);    // B k-chunk offset

    // --- stage scales: s_sc[g*128 + col] = scales[(bn+col)*16 + g] ---
    for (int i = tid; i < GROUPS * 128; i += 512) {
        int g = i >> 7, c = i & 127;
        s_sc[i] = __ldg(&scales[(size_t)(bn + c) * GROUPS + g]);
    }

    int   accg[2][4][4];
    float acct[2][4][4];
#pragma unroll
    for (int mi = 0; mi < 2; ++mi)
#pragma unroll
        for (int ni = 0; ni < 4; ++ni)
#pragma unroll
            for (int c = 0; c < 4; ++c) { accg[mi][ni][c] = 0; acct[mi][ni][c] = 0.f; }

    // --- prologue: prefetch kb = 0,1,2 ---
#pragma unroll
    for (int kb = 0; kb < 3; ++kb) {
        const uint32_t so = (uint32_t)kb * STGB;
        const size_t go = (size_t)kb * BKB;
        cp_async16(dA0 + so, Ar0 + go);
        cp_async16(dA1 + so, Ar1 + go);
        cp_async16(dB0 + so, Br0 + go);
        cp_async16(dB1 + so, Br1 + go);
        cp_commit();
    }

    for (int kb = 0; kb < NKB; ++kb) {
        cp_wait2();
        __syncthreads();

        const uint32_t sAc = sA + (uint32_t)(kb & 3) * STGB;
        const uint32_t sBc = sB + (uint32_t)(kb & 3) * STGB;

#pragma unroll
        for (int k = 0; k < 4; ++k) {            // 4 x k32 per stage
            unsigned a[2][4], b[4][2];
#pragma unroll
            for (int mi = 0; mi < 2; ++mi) {
                uint32_t addr = sAc + arow128[mi] +
                                ((((uint32_t)(k << 1) + aq) ^ arow7[mi]) << 4);
                ldmx4(a[mi][0], a[mi][1], a[mi][2], a[mi][3], addr);
            }
#pragma unroll
            for (int p = 0; p < 2; ++p) {
                uint32_t addr = sBc + brow128[p] +
                                ((((uint32_t)(k << 1) + bq) ^ brow7[p]) << 4);
                ldmx4(b[2 * p][0], b[2 * p][1], b[2 * p + 1][0], b[2 * p + 1][1], addr);
            }
#pragma unroll
            for (int mi = 0; mi < 2; ++mi)
#pragma unroll
                for (int ni = 0; ni < 4; ++ni) {
                    int* c = accg[mi][ni];
                    asm volatile(
                        "mma.sync.aligned.m16n8k32.row.col.s32.s8.s8.s32 "
                        "{%0,%1,%2,%3},{%4,%5,%6,%7},{%8,%9},{%0,%1,%2,%3};\n"
                        : "+r"(c[0]), "+r"(c[1]), "+r"(c[2]), "+r"(c[3])
                        : "r"(a[mi][0]), "r"(a[mi][1]), "r"(a[mi][2]), "r"(a[mi][3]),
                          "r"(b[ni][0]), "r"(b[ni][1]));
                }
        }

        // fold group scale every 256 K (2 kb) — exact (|partial| < 2^24)
        if (kb & 1) {
            const int g = kb >> 1;
            const float* sg = s_sc + g * 128;
#pragma unroll
            for (int ni = 0; ni < 4; ++ni) {
                const int c = nbase + ni * 8 + ((lane & 3) << 1);
                const float s0 = sg[c];
                const float s1 = sg[c + 1];
#pragma unroll
                for (int mi = 0; mi < 2; ++mi) {
                    acct[mi][ni][0] = fmaf(s0, (float)accg[mi][ni][0], acct[mi][ni][0]);
                    acct[mi][ni][1] = fmaf(s1, (float)accg[mi][ni][1], acct[mi][ni][1]);
                    acct[mi][ni][2] = fmaf(s0, (float)accg[mi][ni][2], acct[mi][ni][2]);
                    acct[mi][ni][3] = fmaf(s1, (float)accg[mi][ni][3], acct[mi][ni][3]);
                    accg[mi][ni][0] = 0; accg[mi][ni][1] = 0;
                    accg[mi][ni][2] = 0; accg[mi][ni][3] = 0;
                }
            }
        }

        // prefetch kb+3 into stage (kb+3)&3
        if (kb + 3 < NKB) {
            const uint32_t so = (uint32_t)((kb + 3) & 3) * STGB;
            const size_t go = (size_t)(kb + 3) * BKB;
            cp_async16(dA0 + so, Ar0 + go);
            cp_async16(dA1 + so, Ar1 + go);
            cp_async16(dB0 + so, Br0 + go);
            cp_async16(dB1 + so, Br1 + go);
        }
        cp_commit();
    }

    // epilogue: out[t,o] = sx_t * (acct - zp_t * corr_o)
#pragma unroll
    for (int mi = 0; mi < 2; ++mi) {
        const int row0 = bm + mbase + mi * 16 + (lane >> 2);
        const int row1 = row0 + 8;
        const float sx0 = __ldg(&g_sx[row0]), zp0 = __ldg(&g_zp[row0]);
        const float sx1 = __ldg(&g_sx[row1]), zp1 = __ldg(&g_zp[row1]);
#pragma unroll
        for (int ni = 0; ni < 4; ++ni) {
            const int col = bn + nbase + ni * 8 + ((lane & 3) << 1);
            const float c0 = __ldg(&g_corr[col]);
            const float c1 = __ldg(&g_corr[col + 1]);
            float2 v0 = make_float2(sx0 * (acct[mi][ni][0] - zp0 * c0),
                                    sx0 * (acct[mi][ni][1] - zp0 * c1));
            float2 v1 = make_float2(sx1 * (acct[mi][ni][2] - zp1 * c0),
                                    sx1 * (acct[mi][ni][3] - zp1 * c1));
            *reinterpret_cast<float2*>(out + (size_t)row0 * O_DIM + col) = v0;
            *reinterpret_cast<float2*>(out + (size_t)row1 * O_DIM + col) = v1;
        }
    }
}

#define SMEM_NEED (2 * NSTG * STGB + GROUPS * 128 * 4 + 256)

// ============================================================
extern "C" void kernel_launch(void* const* d_in, const int* in_sizes, int n_in,
                              void* d_out, int out_size) {
    const float* x      = (const float*)d_in[0];
    const int*   w      = (const int*)  d_in[1];
    const float* scales = (const float*)d_in[2];
    const float* zeros  = (const float*)d_in[3];
    float* out = (float*)d_out;

    cudaFuncSetAttribute(gemm_kernel, cudaFuncAttributeMaxDynamicSharedMemorySize, SMEM_NEED);

    quant_kernel<<<T_DIM, 256>>>(x);
    wprep_kernel<<<O_DIM, 256>>>(w, scales, zeros);
    gemm_kernel<<<dim3(O_DIM / 128, T_DIM / 128), 512, SMEM_NEED>>>(scales, out);
}

// round 13
// speedup vs baseline: 2.5169x; 2.5169x over previous
#include <cuda_runtime.h>
#include <cuda_bf16.h>
#include <cstdint>

#define T_DIM 8192
#define O_DIM 4096
#define I_DIM 4096
#define GROUPS 16   // I_DIM / 256

// ---- scratch (allocation-free rule: __device__ globals) ----
__device__ __nv_bfloat16 g_A[(size_t)T_DIM * I_DIM];   // 64 MB: (q - zp) per token, exact ints in bf16
__device__ __nv_bfloat16 g_B[(size_t)O_DIM * I_DIM];   // 32 MB: (w - zero) per group, exact ints in bf16
__device__ float        g_sx[T_DIM];                   // per-token scale

// ============================================================
// Kernel 1: per-token asymmetric int8 fake-quant -> a = q - zp (bf16)
// ============================================================
__global__ void quant_kernel(const float* __restrict__ x) {
    const int row = blockIdx.x;
    const int tid = threadIdx.x;
    const float4* xr = reinterpret_cast<const float4*>(x + (size_t)row * I_DIM);

    float4 v[4];
    float mn = 0.0f, mx = 0.0f;   // reference folds 0 into min/max
#pragma unroll
    for (int j = 0; j < 4; ++j) {
        v[j] = xr[tid + j * 256];
        mn = fminf(mn, fminf(fminf(v[j].x, v[j].y), fminf(v[j].z, v[j].w)));
        mx = fmaxf(mx, fmaxf(fmaxf(v[j].x, v[j].y), fmaxf(v[j].z, v[j].w)));
    }
#pragma unroll
    for (int o = 16; o > 0; o >>= 1) {
        mn = fminf(mn, __shfl_xor_sync(0xffffffffu, mn, o));
        mx = fmaxf(mx, __shfl_xor_sync(0xffffffffu, mx, o));
    }
    __shared__ float smn[8], smx[8];
    if ((tid & 31) == 0) { smn[tid >> 5] = mn; smx[tid >> 5] = mx; }
    __syncthreads();
    mn = smn[0]; mx = smx[0];
#pragma unroll
    for (int w = 1; w < 8; ++w) { mn = fminf(mn, smn[w]); mx = fmaxf(mx, smx[w]); }

    const float scale = fmaxf(__fdiv_rn(mx - mn, 255.0f), 1.1920929e-07f);
    const float dmin = __fdiv_rn(mn, scale);
    const float dmax = __fdiv_rn(mx, scale);
    float zp = ((-128.0f + dmin) + (127.0f + dmax) > 0.0f) ? (-128.0f - dmin)
                                                           : (127.0f - dmax);
    zp = rintf(fminf(fmaxf(zp, -128.0f), 127.0f));

    if (tid == 0) g_sx[row] = scale;

    __nv_bfloat16* Ar = g_A + (size_t)row * I_DIM;
#pragma unroll
    for (int j = 0; j < 4; ++j) {
        float e[4] = {v[j].x, v[j].y, v[j].z, v[j].w};
        __nv_bfloat16 bv[4];
#pragma unroll
        for (int c = 0; c < 4; ++c) {
            float q = rintf(__fdiv_rn(e[c], scale)) + zp;
            q = fminf(fmaxf(q, -128.0f), 127.0f);
            bv[c] = __float2bfloat16_rn(q - zp);  // integer in [-255,255]: exact
        }
        *reinterpret_cast<uint2*>(Ar + (size_t)(tid + j * 256) * 4) =
            *reinterpret_cast<uint2*>(bv);
    }
}

// ============================================================
// Kernel 2: weight prep  b = (w - zero[o,g])  (bf16, exact ints)
// ============================================================
__global__ void wprep_kernel(const int* __restrict__ w, const float* __restrict__ zeros) {
    const size_t e = ((size_t)blockIdx.x * 256 + threadIdx.x) * 4;
    const int4 wv = *reinterpret_cast<const int4*>(w + e);
    const int o = (int)(e >> 12);
    const int i = (int)(e & (I_DIM - 1));
    const int g = i >> 8;
    const float z = __ldg(&zeros[o * GROUPS + g]);
    __nv_bfloat16 bv[4];
    bv[0] = __float2bfloat16_rn((float)wv.x - z);
    bv[1] = __float2bfloat16_rn((float)wv.y - z);
    bv[2] = __float2bfloat16_rn((float)wv.z - z);
    bv[3] = __float2bfloat16_rn((float)wv.w - z);
    *reinterpret_cast<uint2*>(g_B + e) = *reinterpret_cast<uint2*>(bv);
}

// ============================================================
// Kernel 3: group-scaled bf16 GEMM (mma.sync + ldmatrix)
//   CTA 128x128, BK=64, 6-stage cp.async ring, 16 warps (32x32),
//   ONE barrier per 2 K-blocks (K=128 of uninterrupted mma issue).
//   Per-group (K=256) integer partials in registers, folded by
//   scale[o,g]; scale_x[t] at the epilogue. All exact.
// ============================================================
#define BKB 128                 // bytes per smem row (64 bf16)
#define NSTG 6
#define STGB (128 * BKB)        // 16 KB per operand stage
#define NKB (I_DIM / 64)        // 64 k-blocks, 4 per group

__device__ __forceinline__ void cp_async16(uint32_t smem, const void* gmem) {
    asm volatile("cp.async.cg.shared.global [%0], [%1], 16;\n" :: "r"(smem), "l"(gmem));
}
__device__ __forceinline__ void cp_commit() { asm volatile("cp.async.commit_group;\n"); }
__device__ __forceinline__ void cp_wait2()  { asm volatile("cp.async.wait_group 2;\n"); }

__device__ __forceinline__ void ldmx4(unsigned& r0, unsigned& r1, unsigned& r2, unsigned& r3,
                                      uint32_t addr) {
    asm volatile("ldmatrix.sync.aligned.m8n8.x4.shared.b16 {%0,%1,%2,%3}, [%4];"
                 : "=r"(r0), "=r"(r1), "=r"(r2), "=r"(r3) : "r"(addr));
}

__global__ void __launch_bounds__(512, 1)
gemm_kernel(const float* __restrict__ scales, float* __restrict__ out) {
    extern __shared__ char smem_dyn[];
    uint32_t raw = (uint32_t)__cvta_generic_to_shared(smem_dyn);
    const uint32_t sA = (raw + 127u) & ~127u;            // 128B-aligned rows
    const uint32_t sB = sA + NSTG * STGB;
    float* s_sc = reinterpret_cast<float*>(smem_dyn + (sB + NSTG * STGB - raw));

    const int tid  = threadIdx.x;
    const int wid  = tid >> 5;
    const int lane = tid & 31;
    const int bm   = blockIdx.y * 128;
    const int bn   = blockIdx.x * 128;

    // warp grid 4(M) x 4(N); warp tile 32x32
    const int mbase = (wid & 3) * 32;
    const int nbase = (wid >> 2) * 32;
    const int q  = lane >> 3;          // ldmatrix address quad
    const int l7 = lane & 7;

    // --- producer indexing: each thread loads rows r0, r0+64, chunk j ---
    const int r0 = tid >> 3;           // 0..63
    const int j  = tid & 7;
    const uint32_t swoff = (uint32_t)((j ^ (r0 & 7)) << 4);
    const uint32_t dA0 = sA + r0 * BKB + swoff;
    const uint32_t dA1 = dA0 + 64 * BKB;          // (r0+64)&7 == r0&7
    const uint32_t dB0 = sB + r0 * BKB + swoff;
    const uint32_t dB1 = dB0 + 64 * BKB;
    const char* Ar0 = (const char*)(g_A + (size_t)(bm + r0) * I_DIM) + j * 16;
    const char* Ar1 = Ar0 + (size_t)64 * I_DIM * 2;
    const char* Br0 = (const char*)(g_B + (size_t)(bn + r0) * I_DIM) + j * 16;
    const char* Br1 = Br0 + (size_t)64 * I_DIM * 2;

    // --- ldmatrix per-lane row constants ---
    uint32_t arow128[2], arow7[2], brow128[2], brow7[2];
#pragma unroll
    for (int mi = 0; mi < 2; ++mi) {
        int r = mbase + mi * 16 + (q & 1) * 8 + l7;
        arow128[mi] = (uint32_t)(r * BKB);
        arow7[mi]   = (uint32_t)(r & 7);
    }
#pragma unroll
    for (int p = 0; p < 2; ++p) {
        int r = nbase + p * 16 + (q >> 1) * 8 + l7;
        brow128[p] = (uint32_t)(r * BKB);
        brow7[p]   = (uint32_t)(r & 7);
    }
    const uint32_t aq = (uint32_t)(q >> 1);   // A k-chunk offset
    const uint32_t bq = (uint32_t)(q & 1);    // B k-chunk offset

    // --- stage scales: s_sc[g*128 + col] = scales[(bn+col)*16 + g] ---
    for (int i = tid; i < GROUPS * 128; i += 512) {
        int g = i >> 7, c = i & 127;
        s_sc[i] = __ldg(&scales[(size_t)(bn + c) * GROUPS + g]);
    }

    float accg[2][4][4], acct[2][4][4];
#pragma unroll
    for (int mi = 0; mi < 2; ++mi)
#pragma unroll
        for (int ni = 0; ni < 4; ++ni)
#pragma unroll
            for (int c = 0; c < 4; ++c) { accg[mi][ni][c] = 0.f; acct[mi][ni][c] = 0.f; }

    // --- prologue: prefetch kb = 0,1,2,3 into stages 0..3 (one commit each) ---
#pragma unroll
    for (int kb = 0; kb < 4; ++kb) {
        const uint32_t so = (uint32_t)kb * STGB;
        const size_t go = (size_t)kb * BKB;
        cp_async16(dA0 + so, Ar0 + go);
        cp_async16(dA1 + so, Ar1 + go);
        cp_async16(dB0 + so, Br0 + go);
        cp_async16(dB1 + so, Br1 + go);
        cp_commit();
    }

    int st = 0;   // stage of kb = 2*kb2 ; cycles 0,2,4
    for (int kb2 = 0; kb2 < NKB / 2; ++kb2) {
        // stages st, st+1 complete (own groups), publish cross-thread
        cp_wait2();
        __syncthreads();

        // --- prefetch the next two k-blocks immediately (overlaps compute) ---
        {
            const int pk0 = 2 * kb2 + 4;
            const int ps0 = (st + 4 >= NSTG) ? st + 4 - NSTG : st + 4;  // even
            if (pk0 < NKB) {
                const uint32_t so = (uint32_t)ps0 * STGB;
                const size_t go = (size_t)pk0 * BKB;
                cp_async16(dA0 + so, Ar0 + go);
                cp_async16(dA1 + so, Ar1 + go);
                cp_async16(dB0 + so, Br0 + go);
                cp_async16(dB1 + so, Br1 + go);
            }
            cp_commit();
            if (pk0 + 1 < NKB) {
                const uint32_t so = (uint32_t)(ps0 + 1) * STGB;
                const size_t go = (size_t)(pk0 + 1) * BKB;
                cp_async16(dA0 + so, Ar0 + go);
                cp_async16(dA1 + so, Ar1 + go);
                cp_async16(dB0 + so, Br0 + go);
                cp_async16(dB1 + so, Br1 + go);
            }
            cp_commit();
        }

        // --- compute 2 k-blocks (K=128) without any barrier ---
#pragma unroll
        for (int h = 0; h < 2; ++h) {
            const uint32_t sAc = sA + (uint32_t)(st + h) * STGB;
            const uint32_t sBc = sB + (uint32_t)(st + h) * STGB;

#pragma unroll
            for (int k16 = 0; k16 < 4; ++k16) {
                unsigned a[2][4], b[4][2];
#pragma unroll
                for (int mi = 0; mi < 2; ++mi) {
                    uint32_t addr = sAc + arow128[mi] +
                                    ((((uint32_t)(k16 << 1) + aq) ^ arow7[mi]) << 4);
                    ldmx4(a[mi][0], a[mi][1], a[mi][2], a[mi][3], addr);
                }
#pragma unroll
                for (int p = 0; p < 2; ++p) {
                    uint32_t addr = sBc + brow128[p] +
                                    ((((uint32_t)(k16 << 1) + bq) ^ brow7[p]) << 4);
                    ldmx4(b[2 * p][0], b[2 * p][1], b[2 * p + 1][0], b[2 * p + 1][1], addr);
                }
#pragma unroll
                for (int mi = 0; mi < 2; ++mi)
#pragma unroll
                    for (int ni = 0; ni < 4; ++ni) {
                        float* c = accg[mi][ni];
                        asm volatile(
                            "mma.sync.aligned.m16n8k16.row.col.f32.bf16.bf16.f32 "
                            "{%0,%1,%2,%3},{%4,%5,%6,%7},{%8,%9},{%0,%1,%2,%3};\n"
                            : "+f"(c[0]), "+f"(c[1]), "+f"(c[2]), "+f"(c[3])
                            : "r"(a[mi][0]), "r"(a[mi][1]), "r"(a[mi][2]), "r"(a[mi][3]),
                              "r"(b[ni][0]), "r"(b[ni][1]));
                    }
            }

            // fold group scale every 256 K (4 kb): at kb = 2*kb2+1 with kb2 odd
            if (h == 1 && (kb2 & 1)) {
                const int g = kb2 >> 1;
                const float* sg = s_sc + g * 128;
#pragma unroll
                for (int ni = 0; ni < 4; ++ni) {
                    const int c = nbase + ni * 8 + ((lane & 3) << 1);
                    const float s0 = sg[c];
                    const float s1 = sg[c + 1];
#pragma unroll
                    for (int mi = 0; mi < 2; ++mi) {
                        acct[mi][ni][0] = fmaf(s0, accg[mi][ni][0], acct[mi][ni][0]);
                        acct[mi][ni][1] = fmaf(s1, accg[mi][ni][1], acct[mi][ni][1]);
                        acct[mi][ni][2] = fmaf(s0, accg[mi][ni][2], acct[mi][ni][2]);
                        acct[mi][ni][3] = fmaf(s1, accg[mi][ni][3], acct[mi][ni][3]);
                        accg[mi][ni][0] = 0.f; accg[mi][ni][1] = 0.f;
                        accg[mi][ni][2] = 0.f; accg[mi][ni][3] = 0.f;
                    }
                }
            }
        }

        st += 2;
        if (st == NSTG) st = 0;
    }

    // epilogue: out[t,o] = scale_x[t] * total
#pragma unroll
    for (int mi = 0; mi < 2; ++mi) {
        const int row0 = bm + mbase + mi * 16 + (lane >> 2);
        const int row1 = row0 + 8;
        const float sx0 = __ldg(&g_sx[row0]);
        const float sx1 = __ldg(&g_sx[row1]);
#pragma unroll
        for (int ni = 0; ni < 4; ++ni) {
            const int col = bn + nbase + ni * 8 + ((lane & 3) << 1);
            float2 v0 = make_float2(sx0 * acct[mi][ni][0], sx0 * acct[mi][ni][1]);
            float2 v1 = make_float2(sx1 * acct[mi][ni][2], sx1 * acct[mi][ni][3]);
            *reinterpret_cast<float2*>(out + (size_t)row0 * O_DIM + col) = v0;
            *reinterpret_cast<float2*>(out + (size_t)row1 * O_DIM + col) = v1;
        }
    }
}

#define SMEM_NEED (2 * NSTG * STGB + GROUPS * 128 * 4 + 256)

// ============================================================
extern "C" void kernel_launch(void* const* d_in, const int* in_sizes, int n_in,
                              void* d_out, int out_size) {
    const float* x      = (const float*)d_in[0];
    const int*   w      = (const int*)  d_in[1];
    const float* scales = (const float*)d_in[2];
    const float* zeros  = (const float*)d_in[3];
    float* out = (float*)d_out;

    cudaFuncSetAttribute(gemm_kernel, cudaFuncAttributeMaxDynamicSharedMemorySize, SMEM_NEED);

    quant_kernel<<<T_DIM, 256>>>(x);
    wprep_kernel<<<(O_DIM * (I_DIM / 4)) / 256, 256>>>(w, zeros);
    gemm_kernel<<<dim3(O_DIM / 128, T_DIM / 128), 512, SMEM_NEED>>>(scales, out);
}

// round 15
// speedup vs baseline: 2.5933x; 1.0304x over previous
#include <cuda_runtime.h>
#include <cuda_bf16.h>
#include <cstdint>

#define T_DIM 8192
#define O_DIM 4096
#define I_DIM 4096
#define GROUPS 16   // I_DIM / 256

// ---- scratch (allocation-free rule: __device__ globals) ----
__device__ __nv_bfloat16 g_A[(size_t)T_DIM * I_DIM];   // 64 MB: (q - zp) per token, exact ints in bf16
__device__ __nv_bfloat16 g_B[(size_t)O_DIM * I_DIM];   // 32 MB: (w - zero) per group, exact ints in bf16
__device__ float        g_sx[T_DIM];                   // per-token scale

// ============================================================
// Kernel 1: per-token asymmetric int8 fake-quant -> a = q - zp (bf16)
// ============================================================
__global__ void quant_kernel(const float* __restrict__ x) {
    const int row = blockIdx.x;
    const int tid = threadIdx.x;
    const float4* xr = reinterpret_cast<const float4*>(x + (size_t)row * I_DIM);

    float4 v[4];
    float mn = 0.0f, mx = 0.0f;   // reference folds 0 into min/max
#pragma unroll
    for (int j = 0; j < 4; ++j) {
        v[j] = xr[tid + j * 256];
        mn = fminf(mn, fminf(fminf(v[j].x, v[j].y), fminf(v[j].z, v[j].w)));
        mx = fmaxf(mx, fmaxf(fmaxf(v[j].x, v[j].y), fmaxf(v[j].z, v[j].w)));
    }
#pragma unroll
    for (int o = 16; o > 0; o >>= 1) {
        mn = fminf(mn, __shfl_xor_sync(0xffffffffu, mn, o));
        mx = fmaxf(mx, __shfl_xor_sync(0xffffffffu, mx, o));
    }
    __shared__ float smn[8], smx[8];
    if ((tid & 31) == 0) { smn[tid >> 5] = mn; smx[tid >> 5] = mx; }
    __syncthreads();
    mn = smn[0]; mx = smx[0];
#pragma unroll
    for (int w = 1; w < 8; ++w) { mn = fminf(mn, smn[w]); mx = fmaxf(mx, smx[w]); }

    const float scale = fmaxf(__fdiv_rn(mx - mn, 255.0f), 1.1920929e-07f);
    const float dmin = __fdiv_rn(mn, scale);
    const float dmax = __fdiv_rn(mx, scale);
    float zp = ((-128.0f + dmin) + (127.0f + dmax) > 0.0f) ? (-128.0f - dmin)
                                                           : (127.0f - dmax);
    zp = rintf(fminf(fmaxf(zp, -128.0f), 127.0f));

    if (tid == 0) g_sx[row] = scale;

    __nv_bfloat16* Ar = g_A + (size_t)row * I_DIM;
#pragma unroll
    for (int j = 0; j < 4; ++j) {
        float e[4] = {v[j].x, v[j].y, v[j].z, v[j].w};
        __nv_bfloat16 bv[4];
#pragma unroll
        for (int c = 0; c < 4; ++c) {
            float q = rintf(__fdiv_rn(e[c], scale)) + zp;
            q = fminf(fmaxf(q, -128.0f), 127.0f);
            bv[c] = __float2bfloat16_rn(q - zp);  // integer in [-255,255]: exact
        }
        *reinterpret_cast<uint2*>(Ar + (size_t)(tid + j * 256) * 4) =
            *reinterpret_cast<uint2*>(bv);
    }
}

// ============================================================
// Kernel 2: weight prep  b = (w - zero[o,g])  (bf16, exact ints)
// ============================================================
__global__ void wprep_kernel(const int* __restrict__ w, const float* __restrict__ zeros) {
    const size_t e = ((size_t)blockIdx.x * 256 + threadIdx.x) * 4;
    const int4 wv = *reinterpret_cast<const int4*>(w + e);
    const int o = (int)(e >> 12);
    const int i = (int)(e & (I_DIM - 1));
    const int g = i >> 8;
    const float z = __ldg(&zeros[o * GROUPS + g]);
    __nv_bfloat16 bv[4];
    bv[0] = __float2bfloat16_rn((float)wv.x - z);
    bv[1] = __float2bfloat16_rn((float)wv.y - z);
    bv[2] = __float2bfloat16_rn((float)wv.z - z);
    bv[3] = __float2bfloat16_rn((float)wv.w - z);
    *reinterpret_cast<uint2*>(g_B + e) = *reinterpret_cast<uint2*>(bv);
}

// ============================================================
// Kernel 3: group-scaled bf16 GEMM (mma.sync + ldmatrix)
//   CTA 128x128, BK=64, 6-stage cp.async ring, 8 warps (64x32 each),
//   one barrier per 2 K-blocks. Per-group (K=256) integer partials in
//   registers, folded by scale[o,g]; scale_x[t] at the epilogue. Exact.
// ============================================================
#define BKB 128                 // bytes per smem row (64 bf16)
#define NSTG 6
#define STGB (128 * BKB)        // 16 KB per operand stage
#define NKB (I_DIM / 64)        // 64 k-blocks, 4 per group

__device__ __forceinline__ void cp_async16(uint32_t smem, const void* gmem) {
    asm volatile("cp.async.cg.shared.global [%0], [%1], 16;\n" :: "r"(smem), "l"(gmem));
}
__device__ __forceinline__ void cp_commit() { asm volatile("cp.async.commit_group;\n"); }
__device__ __forceinline__ void cp_wait2()  { asm volatile("cp.async.wait_group 2;\n"); }

__device__ __forceinline__ void ldmx4(unsigned& r0, unsigned& r1, unsigned& r2, unsigned& r3,
                                      uint32_t addr) {
    asm volatile("ldmatrix.sync.aligned.m8n8.x4.shared.b16 {%0,%1,%2,%3}, [%4];"
                 : "=r"(r0), "=r"(r1), "=r"(r2), "=r"(r3) : "r"(addr));
}

__global__ void __launch_bounds__(256, 1)
gemm_kernel(const float* __restrict__ scales, float* __restrict__ out) {
    extern __shared__ char smem_dyn[];
    uint32_t raw = (uint32_t)__cvta_generic_to_shared(smem_dyn);
    const uint32_t sA = (raw + 127u) & ~127u;            // 128B-aligned rows
    const uint32_t sB = sA + NSTG * STGB;
    float* s_sc = reinterpret_cast<float*>(smem_dyn + (sB + NSTG * STGB - raw));

    const int tid  = threadIdx.x;
    const int wid  = tid >> 5;
    const int lane = tid & 31;
    const int bm   = blockIdx.y * 128;
    const int bn   = blockIdx.x * 128;

    // warp grid 2(M) x 4(N); warp tile 64x32
    const int mbase = (wid & 1) * 64;
    const int nbase = (wid >> 1) * 32;
    const int q  = lane >> 3;          // ldmatrix address quad
    const int l7 = lane & 7;

    // --- producer indexing: each thread loads rows r0+32i (i=0..3), chunk j ---
    const int r0 = tid >> 3;           // 0..31
    const int j  = tid & 7;
    const uint32_t swoff = (uint32_t)((j ^ (r0 & 7)) << 4);
    const uint32_t dA0 = sA + r0 * BKB + swoff;   // rows r0+32i share (r&7)
    const uint32_t dB0 = sB + r0 * BKB + swoff;
    const char* Ar0 = (const char*)(g_A + (size_t)(bm + r0) * I_DIM) + j * 16;
    const char* Br0 = (const char*)(g_B + (size_t)(bn + r0) * I_DIM) + j * 16;
    const size_t rstep = (size_t)32 * I_DIM * 2;   // 32 rows of bf16

    // --- ldmatrix per-lane row constants ---
    uint32_t arow128[4], arow7[4], brow128[2], brow7[2];
#pragma unroll
    for (int mi = 0; mi < 4; ++mi) {
        int r = mbase + mi * 16 + (q & 1) * 8 + l7;
        arow128[mi] = (uint32_t)(r * BKB);
        arow7[mi]   = (uint32_t)(r & 7);
    }
#pragma unroll
    for (int p = 0; p < 2; ++p) {
        int r = nbase + p * 16 + (q >> 1) * 8 + l7;
        brow128[p] = (uint32_t)(r * BKB);
        brow7[p]   = (uint32_t)(r & 7);
    }
    const uint32_t aq = (uint32_t)(q >> 1);   // A k-chunk offset
    const uint32_t bq = (uint32_t)(q & 1);    // B k-chunk offset

    // --- stage scales: s_sc[g*128 + col] = scales[(bn+col)*16 + g] ---
    for (int i = tid; i < GROUPS * 128; i += 256) {
        int g = i >> 7, c = i & 127;
        s_sc[i] = __ldg(&scales[(size_t)(bn + c) * GROUPS + g]);
    }

    float accg[4][4][4], acct[4][4][4];
#pragma unroll
    for (int mi = 0; mi < 4; ++mi)
#pragma unroll
        for (int ni = 0; ni < 4; ++ni)
#pragma unroll
            for (int c = 0; c < 4; ++c) { accg[mi][ni][c] = 0.f; acct[mi][ni][c] = 0.f; }

    // --- prologue: prefetch kb = 0,1,2,3 into stages 0..3 (one commit each) ---
#pragma unroll
    for (int kb = 0; kb < 4; ++kb) {
        const uint32_t so = (uint32_t)kb * STGB;
        const size_t go = (size_t)kb * BKB;
#pragma unroll
        for (int i = 0; i < 4; ++i) {
            cp_async16(dA0 + so + i * 32 * BKB, Ar0 + go + i * rstep);
            cp_async16(dB0 + so + i * 32 * BKB, Br0 + go + i * rstep);
        }
        cp_commit();
    }

    int st = 0;   // stage of kb = 2*kb2 ; cycles 0,2,4
    for (int kb2 = 0; kb2 < NKB / 2; ++kb2) {
        // stages st, st+1 complete (own groups), publish cross-thread
        cp_wait2();
        __syncthreads();

        // --- prefetch the next two k-blocks immediately (overlaps compute) ---
        {
            const int pk0 = 2 * kb2 + 4;
            const int ps0 = (st + 4 >= NSTG) ? st + 4 - NSTG : st + 4;  // even
            if (pk0 < NKB) {
                const uint32_t so = (uint32_t)ps0 * STGB;
                const size_t go = (size_t)pk0 * BKB;
#pragma unroll
                for (int i = 0; i < 4; ++i) {
                    cp_async16(dA0 + so + i * 32 * BKB, Ar0 + go + i * rstep);
                    cp_async16(dB0 + so + i * 32 * BKB, Br0 + go + i * rstep);
                }
            }
            cp_commit();
            if (pk0 + 1 < NKB) {
                const uint32_t so = (uint32_t)(ps0 + 1) * STGB;
                const size_t go = (size_t)(pk0 + 1) * BKB;
#pragma unroll
                for (int i = 0; i < 4; ++i) {
                    cp_async16(dA0 + so + i * 32 * BKB, Ar0 + go + i * rstep);
                    cp_async16(dB0 + so + i * 32 * BKB, Br0 + go + i * rstep);
                }
            }
            cp_commit();
        }

        // --- compute 2 k-blocks (K=128) without any barrier ---
#pragma unroll
        for (int h = 0; h < 2; ++h) {
            const uint32_t sAc = sA + (uint32_t)(st + h) * STGB;
            const uint32_t sBc = sB + (uint32_t)(st + h) * STGB;

#pragma unroll
            for (int k16 = 0; k16 < 4; ++k16) {
                unsigned a[4][4], b[4][2];
#pragma unroll
                for (int mi = 0; mi < 4; ++mi) {
                    uint32_t addr = sAc + arow128[mi] +
                                    ((((uint32_t)(k16 << 1) + aq) ^ arow7[mi]) << 4);
                    ldmx4(a[mi][0], a[mi][1], a[mi][2], a[mi][3], addr);
                }
#pragma unroll
                for (int p = 0; p < 2; ++p) {
                    uint32_t addr = sBc + brow128[p] +
                                    ((((uint32_t)(k16 << 1) + bq) ^ brow7[p]) << 4);
                    ldmx4(b[2 * p][0], b[2 * p][1], b[2 * p + 1][0], b[2 * p + 1][1], addr);
                }
#pragma unroll
                for (int mi = 0; mi < 4; ++mi)
#pragma unroll
                    for (int ni = 0; ni < 4; ++ni) {
                        float* c = accg[mi][ni];
                        asm volatile(
                            "mma.sync.aligned.m16n8k16.row.col.f32.bf16.bf16.f32 "
                            "{%0,%1,%2,%3},{%4,%5,%6,%7},{%8,%9},{%0,%1,%2,%3};\n"
                            : "+f"(c[0]), "+f"(c[1]), "+f"(c[2]), "+f"(c[3])
                            : "r"(a[mi][0]), "r"(a[mi][1]), "r"(a[mi][2]), "r"(a[mi][3]),
                              "r"(b[ni][0]), "r"(b[ni][1]));
                    }
            }

            // fold group scale every 256 K (4 kb): at kb = 2*kb2+1 with kb2 odd
            if (h == 1 && (kb2 & 1)) {
                const int g = kb2 >> 1;
                const float* sg = s_sc + g * 128;
#pragma unroll
                for (int ni = 0; ni < 4; ++ni) {
                    const int c = nbase + ni * 8 + ((lane & 3) << 1);
                    const float s0 = sg[c];
                    const float s1 = sg[c + 1];
#pragma unroll
                    for (int mi = 0; mi < 4; ++mi) {
                        acct[mi][ni][0] = fmaf(s0, accg[mi][ni][0], acct[mi][ni][0]);
                        acct[mi][ni][1] = fmaf(s1, accg[mi][ni][1], acct[mi][ni][1]);
                        acct[mi][ni][2] = fmaf(s0, accg[mi][ni][2], acct[mi][ni][2]);
                        acct[mi][ni][3] = fmaf(s1, accg[mi][ni][3], acct[mi][ni][3]);
                        accg[mi][ni][0] = 0.f; accg[mi][ni][1] = 0.f;
                        accg[mi][ni][2] = 0.f; accg[mi][ni][3] = 0.f;
                    }
                }
            }
        }

        st += 2;
        if (st == NSTG) st = 0;
    }

    // epilogue: out[t,o] = scale_x[t] * total
#pragma unroll
    for (int mi = 0; mi < 4; ++mi) {
        const int row0 = bm + mbase + mi * 16 + (lane >> 2);
        const int row1 = row0 + 8;
        const float sx0 = __ldg(&g_sx[row0]);
        const float sx1 = __ldg(&g_sx[row1]);
#pragma unroll
        for (int ni = 0; ni < 4; ++ni) {
            const int col = bn + nbase + ni * 8 + ((lane & 3) << 1);
            float2 v0 = make_float2(sx0 * acct[mi][ni][0], sx0 * acct[mi][ni][1]);
            float2 v1 = make_float2(sx1 * acct[mi][ni][2], sx1 * acct[mi][ni][3]);
            *reinterpret_cast<float2*>(out + (size_t)row0 * O_DIM + col) = v0;
            *reinterpret_cast<float2*>(out + (size_t)row1 * O_DIM + col) = v1;
        }
    }
}

#define SMEM_NEED (2 * NSTG * STGB + GROUPS * 128 * 4 + 256)

// ============================================================
extern "C" void kernel_launch(void* const* d_in, const int* in_sizes, int n_in,
                              void* d_out, int out_size) {
    const float* x      = (const float*)d_in[0];
    const int*   w      = (const int*)  d_in[1];
    const float* scales = (const float*)d_in[2];
    const float* zeros  = (const float*)d_in[3];
    float* out = (float*)d_out;

    cudaFuncSetAttribute(gemm_kernel, cudaFuncAttributeMaxDynamicSharedMemorySize, SMEM_NEED);

    quant_kernel<<<T_DIM, 256>>>(x);
    wprep_kernel<<<(O_DIM * (I_DIM / 4)) / 256, 256>>>(w, zeros);
    gemm_kernel<<<dim3(O_DIM / 128, T_DIM / 128), 256, SMEM_NEED>>>(scales, out);
}

// round 16
// speedup vs baseline: 2.5935x; 1.0001x over previous
#include <cuda_runtime.h>
#include <cuda_bf16.h>
#include <cstdint>

#define T_DIM 8192
#define O_DIM 4096
#define I_DIM 4096
#define GROUPS 16   // I_DIM / 256

// ---- scratch (allocation-free rule: __device__ globals) ----
__device__ __nv_bfloat16 g_A[(size_t)T_DIM * I_DIM];   // 64 MB: (q - zp) per token, exact ints in bf16
__device__ __nv_bfloat16 g_B[(size_t)O_DIM * I_DIM];   // 32 MB: (w - zero) per group, exact ints in bf16
__device__ float        g_sx[T_DIM];                   // per-token scale

// ============================================================
// Kernel 1: per-token asymmetric int8 fake-quant -> a = q - zp (bf16)
// ============================================================
__global__ void quant_kernel(const float* __restrict__ x) {
    const int row = blockIdx.x;
    const int tid = threadIdx.x;
    const float4* xr = reinterpret_cast<const float4*>(x + (size_t)row * I_DIM);

    float4 v[4];
    float mn = 0.0f, mx = 0.0f;   // reference folds 0 into min/max
#pragma unroll
    for (int j = 0; j < 4; ++j) {
        v[j] = xr[tid + j * 256];
        mn = fminf(mn, fminf(fminf(v[j].x, v[j].y), fminf(v[j].z, v[j].w)));
        mx = fmaxf(mx, fmaxf(fmaxf(v[j].x, v[j].y), fmaxf(v[j].z, v[j].w)));
    }
#pragma unroll
    for (int o = 16; o > 0; o >>= 1) {
        mn = fminf(mn, __shfl_xor_sync(0xffffffffu, mn, o));
        mx = fmaxf(mx, __shfl_xor_sync(0xffffffffu, mx, o));
    }
    __shared__ float smn[8], smx[8];
    if ((tid & 31) == 0) { smn[tid >> 5] = mn; smx[tid >> 5] = mx; }
    __syncthreads();
    mn = smn[0]; mx = smx[0];
#pragma unroll
    for (int w = 1; w < 8; ++w) { mn = fminf(mn, smn[w]); mx = fmaxf(mx, smx[w]); }

    const float scale = fmaxf(__fdiv_rn(mx - mn, 255.0f), 1.1920929e-07f);
    const float dmin = __fdiv_rn(mn, scale);
    const float dmax = __fdiv_rn(mx, scale);
    float zp = ((-128.0f + dmin) + (127.0f + dmax) > 0.0f) ? (-128.0f - dmin)
                                                           : (127.0f - dmax);
    zp = rintf(fminf(fmaxf(zp, -128.0f), 127.0f));

    if (tid == 0) g_sx[row] = scale;

    __nv_bfloat16* Ar = g_A + (size_t)row * I_DIM;
#pragma unroll
    for (int j = 0; j < 4; ++j) {
        float e[4] = {v[j].x, v[j].y, v[j].z, v[j].w};
        __nv_bfloat16 bv[4];
#pragma unroll
        for (int c = 0; c < 4; ++c) {
            float q = rintf(__fdiv_rn(e[c], scale)) + zp;
            q = fminf(fmaxf(q, -128.0f), 127.0f);
            bv[c] = __float2bfloat16_rn(q - zp);  // integer in [-255,255]: exact
        }
        *reinterpret_cast<uint2*>(Ar + (size_t)(tid + j * 256) * 4) =
            *reinterpret_cast<uint2*>(bv);
    }
}

// ============================================================
// Kernel 2: weight prep  b = (w - zero[o,g])  (bf16, exact ints)
// ============================================================
__global__ void wprep_kernel(const int* __restrict__ w, const float* __restrict__ zeros) {
    const size_t e = ((size_t)blockIdx.x * 256 + threadIdx.x) * 4;
    const int4 wv = *reinterpret_cast<const int4*>(w + e);
    const int o = (int)(e >> 12);
    const int i = (int)(e & (I_DIM - 1));
    const int g = i >> 8;
    const float z = __ldg(&zeros[o * GROUPS + g]);
    __nv_bfloat16 bv[4];
    bv[0] = __float2bfloat16_rn((float)wv.x - z);
    bv[1] = __float2bfloat16_rn((float)wv.y - z);
    bv[2] = __float2bfloat16_rn((float)wv.z - z);
    bv[3] = __float2bfloat16_rn((float)wv.w - z);
    *reinterpret_cast<uint2*>(g_B + e) = *reinterpret_cast<uint2*>(bv);
}

// ============================================================
// Kernel 3: group-scaled bf16 GEMM (mma.sync + ldmatrix)
//   CTA 128x128, BK=64, 6-stage cp.async ring, 8 warps (64x32 each),
//   one barrier per 2 K-blocks, REGISTER-LEVEL fragment double-buffer
//   (LDSM of step s+1 overlaps HMMA of step s). Exact group-scale
//   dual accumulators; scale_x[t] at the epilogue.
// ============================================================
#define BKB 128                 // bytes per smem row (64 bf16)
#define NSTG 6
#define STGB (128 * BKB)        // 16 KB per operand stage
#define NKB (I_DIM / 64)        // 64 k-blocks, 4 per group

__device__ __forceinline__ void cp_async16(uint32_t smem, const void* gmem) {
    asm volatile("cp.async.cg.shared.global [%0], [%1], 16;\n" :: "r"(smem), "l"(gmem));
}
__device__ __forceinline__ void cp_commit() { asm volatile("cp.async.commit_group;\n"); }
__device__ __forceinline__ void cp_wait2()  { asm volatile("cp.async.wait_group 2;\n"); }

__device__ __forceinline__ void ldmx4(unsigned& r0, unsigned& r1, unsigned& r2, unsigned& r3,
                                      uint32_t addr) {
    asm volatile("ldmatrix.sync.aligned.m8n8.x4.shared.b16 {%0,%1,%2,%3}, [%4];"
                 : "=r"(r0), "=r"(r1), "=r"(r2), "=r"(r3) : "r"(addr));
}

__global__ void __launch_bounds__(256, 1)
gemm_kernel(const float* __restrict__ scales, float* __restrict__ out) {
    extern __shared__ char smem_dyn[];
    uint32_t raw = (uint32_t)__cvta_generic_to_shared(smem_dyn);
    const uint32_t sA = (raw + 127u) & ~127u;            // 128B-aligned rows
    const uint32_t sB = sA + NSTG * STGB;
    float* s_sc = reinterpret_cast<float*>(smem_dyn + (sB + NSTG * STGB - raw));

    const int tid  = threadIdx.x;
    const int wid  = tid >> 5;
    const int lane = tid & 31;
    const int bm   = blockIdx.y * 128;
    const int bn   = blockIdx.x * 128;

    // warp grid 2(M) x 4(N); warp tile 64x32
    const int mbase = (wid & 1) * 64;
    const int nbase = (wid >> 1) * 32;
    const int q  = lane >> 3;          // ldmatrix address quad
    const int l7 = lane & 7;

    // --- producer indexing: each thread loads rows r0+32i (i=0..3), chunk j ---
    const int r0 = tid >> 3;           // 0..31
    const int j  = tid & 7;
    const uint32_t swoff = (uint32_t)((j ^ (r0 & 7)) << 4);
    const uint32_t dA0 = sA + r0 * BKB + swoff;   // rows r0+32i share (r&7)
    const uint32_t dB0 = sB + r0 * BKB + swoff;
    const char* Ar0 = (const char*)(g_A + (size_t)(bm + r0) * I_DIM) + j * 16;
    const char* Br0 = (const char*)(g_B + (size_t)(bn + r0) * I_DIM) + j * 16;
    const size_t rstep = (size_t)32 * I_DIM * 2;   // 32 rows of bf16

    // --- ldmatrix per-lane row constants ---
    uint32_t arow128[4], arow7[4], brow128[2], brow7[2];
#pragma unroll
    for (int mi = 0; mi < 4; ++mi) {
        int r = mbase + mi * 16 + (q & 1) * 8 + l7;
        arow128[mi] = (uint32_t)(r * BKB);
        arow7[mi]   = (uint32_t)(r & 7);
    }
#pragma unroll
    for (int p = 0; p < 2; ++p) {
        int r = nbase + p * 16 + (q >> 1) * 8 + l7;
        brow128[p] = (uint32_t)(r * BKB);
        brow7[p]   = (uint32_t)(r & 7);
    }
    const uint32_t aq = (uint32_t)(q >> 1);   // A k-chunk offset
    const uint32_t bq = (uint32_t)(q & 1);    // B k-chunk offset

    // --- stage scales: s_sc[g*128 + col] = scales[(bn+col)*16 + g] ---
    for (int i = tid; i < GROUPS * 128; i += 256) {
        int g = i >> 7, c = i & 127;
        s_sc[i] = __ldg(&scales[(size_t)(bn + c) * GROUPS + g]);
    }

    float accg[4][4][4], acct[4][4][4];
#pragma unroll
    for (int mi = 0; mi < 4; ++mi)
#pragma unroll
        for (int ni = 0; ni < 4; ++ni)
#pragma unroll
            for (int c = 0; c < 4; ++c) { accg[mi][ni][c] = 0.f; acct[mi][ni][c] = 0.f; }

    // --- prologue: prefetch kb = 0,1,2,3 into stages 0..3 (one commit each) ---
#pragma unroll
    for (int kb = 0; kb < 4; ++kb) {
        const uint32_t so = (uint32_t)kb * STGB;
        const size_t go = (size_t)kb * BKB;
#pragma unroll
        for (int i = 0; i < 4; ++i) {
            cp_async16(dA0 + so + i * 32 * BKB, Ar0 + go + i * rstep);
            cp_async16(dB0 + so + i * 32 * BKB, Br0 + go + i * rstep);
        }
        cp_commit();
    }

    // fragment double buffers
    unsigned fa[2][4][4], fb[2][4][2];

#define LDFRAG(buf, sAc, sBc, k16) do {                                         \
        _Pragma("unroll")                                                       \
        for (int mi = 0; mi < 4; ++mi) {                                        \
            uint32_t addr = (sAc) + arow128[mi] +                               \
                            ((((uint32_t)((k16) << 1) + aq) ^ arow7[mi]) << 4); \
            ldmx4(fa[buf][mi][0], fa[buf][mi][1], fa[buf][mi][2],               \
                  fa[buf][mi][3], addr);                                        \
        }                                                                       \
        _Pragma("unroll")                                                       \
        for (int p = 0; p < 2; ++p) {                                           \
            uint32_t addr = (sBc) + brow128[p] +                                \
                            ((((uint32_t)((k16) << 1) + bq) ^ brow7[p]) << 4);  \
            ldmx4(fb[buf][2 * p][0], fb[buf][2 * p][1],                         \
                  fb[buf][2 * p + 1][0], fb[buf][2 * p + 1][1], addr);          \
        }                                                                       \
    } while (0)

#define DOMMA(buf) do {                                                         \
        _Pragma("unroll")                                                       \
        for (int mi = 0; mi < 4; ++mi)                                          \
            _Pragma("unroll")                                                   \
            for (int ni = 0; ni < 4; ++ni) {                                    \
                float* c = accg[mi][ni];                                        \
                asm volatile(                                                   \
                    "mma.sync.aligned.m16n8k16.row.col.f32.bf16.bf16.f32 "      \
                    "{%0,%1,%2,%3},{%4,%5,%6,%7},{%8,%9},{%0,%1,%2,%3};\n"      \
                    : "+f"(c[0]), "+f"(c[1]), "+f"(c[2]), "+f"(c[3])            \
                    : "r"(fa[buf][mi][0]), "r"(fa[buf][mi][1]),                 \
                      "r"(fa[buf][mi][2]), "r"(fa[buf][mi][3]),                 \
                      "r"(fb[buf][ni][0]), "r"(fb[buf][ni][1]));                \
            }                                                                   \
    } while (0)

    int st = 0;   // stage of kb = 2*kb2 ; cycles 0,2,4
    for (int kb2 = 0; kb2 < NKB / 2; ++kb2) {
        // stages st, st+1 complete (own groups), publish cross-thread
        cp_wait2();
        __syncthreads();

        // --- prefetch the next two k-blocks immediately (overlaps compute) ---
        {
            const int pk0 = 2 * kb2 + 4;
            const int ps0 = (st + 4 >= NSTG) ? st + 4 - NSTG : st + 4;  // even
            if (pk0 < NKB) {
                const uint32_t so = (uint32_t)ps0 * STGB;
                const size_t go = (size_t)pk0 * BKB;
#pragma unroll
                for (int i = 0; i < 4; ++i) {
                    cp_async16(dA0 + so + i * 32 * BKB, Ar0 + go + i * rstep);
                    cp_async16(dB0 + so + i * 32 * BKB, Br0 + go + i * rstep);
                }
            }
            cp_commit();
            if (pk0 + 1 < NKB) {
                const uint32_t so = (uint32_t)(ps0 + 1) * STGB;
                const size_t go = (size_t)(pk0 + 1) * BKB;
#pragma unroll
                for (int i = 0; i < 4; ++i) {
                    cp_async16(dA0 + so + i * 32 * BKB, Ar0 + go + i * rstep);
                    cp_async16(dB0 + so + i * 32 * BKB, Br0 + go + i * rstep);
                }
            }
            cp_commit();
        }

        // --- compute 2 k-blocks (K=128): 8 k16 steps, frag double-buffered ---
        const uint32_t sAc0 = sA + (uint32_t)st * STGB;
        const uint32_t sBc0 = sB + (uint32_t)st * STGB;
        const uint32_t sAc1 = sAc0 + STGB;
        const uint32_t sBc1 = sBc0 + STGB;

        LDFRAG(0, sAc0, sBc0, 0);
#pragma unroll
        for (int s = 0; s < 8; ++s) {
            const int cb = s & 1;
            if (s < 7) {
                const int k2 = (s + 1) & 3;
                if (((s + 1) >> 2) == 0) { LDFRAG(!(s & 1) ? 1 : 0, sAc0, sBc0, k2); }
                else                     { LDFRAG(!(s & 1) ? 1 : 0, sAc1, sBc1, k2); }
            }
            DOMMA(cb);
        }

        // fold group scale every 256 K (4 kb): after odd kb2
        if (kb2 & 1) {
            const int g = kb2 >> 1;
            const float* sg = s_sc + g * 128;
#pragma unroll
            for (int ni = 0; ni < 4; ++ni) {
                const int c = nbase + ni * 8 + ((lane & 3) << 1);
                const float s0 = sg[c];
                const float s1 = sg[c + 1];
#pragma unroll
                for (int mi = 0; mi < 4; ++mi) {
                    acct[mi][ni][0] = fmaf(s0, accg[mi][ni][0], acct[mi][ni][0]);
                    acct[mi][ni][1] = fmaf(s1, accg[mi][ni][1], acct[mi][ni][1]);
                    acct[mi][ni][2] = fmaf(s0, accg[mi][ni][2], acct[mi][ni][2]);
                    acct[mi][ni][3] = fmaf(s1, accg[mi][ni][3], acct[mi][ni][3]);
                    accg[mi][ni][0] = 0.f; accg[mi][ni][1] = 0.f;
                    accg[mi][ni][2] = 0.f; accg[mi][ni][3] = 0.f;
                }
            }
        }

        st += 2;
        if (st == NSTG) st = 0;
    }

    // epilogue: out[t,o] = scale_x[t] * total
#pragma unroll
    for (int mi = 0; mi < 4; ++mi) {
        const int row0 = bm + mbase + mi * 16 + (lane >> 2);
        const int row1 = row0 + 8;
        const float sx0 = __ldg(&g_sx[row0]);
        const float sx1 = __ldg(&g_sx[row1]);
#pragma unroll
        for (int ni = 0; ni < 4; ++ni) {
            const int col = bn + nbase + ni * 8 + ((lane & 3) << 1);
            float2 v0 = make_float2(sx0 * acct[mi][ni][0], sx0 * acct[mi][ni][1]);
            float2 v1 = make_float2(sx1 * acct[mi][ni][2], sx1 * acct[mi][ni][3]);
            *reinterpret_cast<float2*>(out + (size_t)row0 * O_DIM + col) = v0;
            *reinterpret_cast<float2*>(out + (size_t)row1 * O_DIM + col) = v1;
        }
    }
}

#define SMEM_NEED (2 * NSTG * STGB + GROUPS * 128 * 4 + 256)

// ============================================================
extern "C" void kernel_launch(void* const* d_in, const int* in_sizes, int n_in,
                              void* d_out, int out_size) {
    const float* x      = (const float*)d_in[0];
    const int*   w      = (const int*)  d_in[1];
    const float* scales = (const float*)d_in[2];
    const float* zeros  = (const float*)d_in[3];
    float* out = (float*)d_out;

    cudaFuncSetAttribute(gemm_kernel, cudaFuncAttributeMaxDynamicSharedMemorySize, SMEM_NEED);

    quant_kernel<<<T_DIM, 256>>>(x);
    wprep_kernel<<<(O_DIM * (I_DIM / 4)) / 256, 256>>>(w, zeros);
    gemm_kernel<<<dim3(O_DIM / 128, T_DIM / 128), 256, SMEM_NEED>>>(scales, out);
}

// round 17
// speedup vs baseline: 2.5990x; 1.0021x over previous
#include <cuda_runtime.h>
#include <cuda_bf16.h>
#include <cstdint>

#define T_DIM 8192
#define O_DIM 4096
#define I_DIM 4096
#define GROUPS 16   // I_DIM / 256

// ---- scratch (allocation-free rule: __device__ globals) ----
__device__ __nv_bfloat16 g_A[(size_t)T_DIM * I_DIM];   // 64 MB: (q - zp) per token, exact ints in bf16
__device__ __nv_bfloat16 g_B[(size_t)O_DIM * I_DIM];   // 32 MB: (w - zero) per group, exact ints in bf16
__device__ float        g_sx[T_DIM];                   // per-token scale

// ============================================================
// Kernel 1 (fused): per-token int8 fake-quant (blocks 0..T-1)
//                   + weight prep b = w - zero (blocks T..)
// ============================================================
#define WPREP_BLOCKS ((O_DIM * (I_DIM / 4)) / 256)   // 16384

__global__ void prep_kernel(const float* __restrict__ x,
                            const int* __restrict__ w,
                            const float* __restrict__ zeros) {
    if (blockIdx.x < T_DIM) {
        // ---------------- per-token activation quant ----------------
        const int row = blockIdx.x;
        const int tid = threadIdx.x;
        const float4* xr = reinterpret_cast<const float4*>(x + (size_t)row * I_DIM);

        float4 v[4];
        float mn = 0.0f, mx = 0.0f;   // reference folds 0 into min/max
#pragma unroll
        for (int j = 0; j < 4; ++j) {
            v[j] = __ldcs(&xr[tid + j * 256]);     // read-once: evict-first
            mn = fminf(mn, fminf(fminf(v[j].x, v[j].y), fminf(v[j].z, v[j].w)));
            mx = fmaxf(mx, fmaxf(fmaxf(v[j].x, v[j].y), fmaxf(v[j].z, v[j].w)));
        }
#pragma unroll
        for (int o = 16; o > 0; o >>= 1) {
            mn = fminf(mn, __shfl_xor_sync(0xffffffffu, mn, o));
            mx = fmaxf(mx, __shfl_xor_sync(0xffffffffu, mx, o));
        }
        __shared__ float smn[8], smx[8];
        if ((tid & 31) == 0) { smn[tid >> 5] = mn; smx[tid >> 5] = mx; }
        __syncthreads();
        mn = smn[0]; mx = smx[0];
#pragma unroll
        for (int wv = 1; wv < 8; ++wv) { mn = fminf(mn, smn[wv]); mx = fmaxf(mx, smx[wv]); }

        const float scale = fmaxf(__fdiv_rn(mx - mn, 255.0f), 1.1920929e-07f);
        const float dmin = __fdiv_rn(mn, scale);
        const float dmax = __fdiv_rn(mx, scale);
        float zp = ((-128.0f + dmin) + (127.0f + dmax) > 0.0f) ? (-128.0f - dmin)
                                                               : (127.0f - dmax);
        zp = rintf(fminf(fmaxf(zp, -128.0f), 127.0f));

        if (tid == 0) g_sx[row] = scale;

        __nv_bfloat16* Ar = g_A + (size_t)row * I_DIM;
#pragma unroll
        for (int j = 0; j < 4; ++j) {
            float e[4] = {v[j].x, v[j].y, v[j].z, v[j].w};
            __nv_bfloat16 bv[4];
#pragma unroll
            for (int c = 0; c < 4; ++c) {
                float q = rintf(__fdiv_rn(e[c], scale)) + zp;
                q = fminf(fmaxf(q, -128.0f), 127.0f);
                bv[c] = __float2bfloat16_rn(q - zp);  // integer in [-255,255]: exact
            }
            *reinterpret_cast<uint2*>(Ar + (size_t)(tid + j * 256) * 4) =
                *reinterpret_cast<uint2*>(bv);
        }
    } else {
        // ---------------- weight prep: b = (w - zero[o,g]) ----------------
        const size_t e = ((size_t)(blockIdx.x - T_DIM) * 256 + threadIdx.x) * 4;
        const int4 wv = __ldcs(reinterpret_cast<const int4*>(w + e));   // read-once
        const int o = (int)(e >> 12);
        const int i = (int)(e & (I_DIM - 1));
        const int g = i >> 8;
        const float z = __ldg(&zeros[o * GROUPS + g]);
        __nv_bfloat16 bv[4];
        bv[0] = __float2bfloat16_rn((float)wv.x - z);
        bv[1] = __float2bfloat16_rn((float)wv.y - z);
        bv[2] = __float2bfloat16_rn((float)wv.z - z);
        bv[3] = __float2bfloat16_rn((float)wv.w - z);
        *reinterpret_cast<uint2*>(g_B + e) = *reinterpret_cast<uint2*>(bv);
    }
}

// ============================================================
// Kernel 2: group-scaled bf16 GEMM (mma.sync + ldmatrix)
//   CTA 128x128, BK=64, 6-stage cp.async ring, 8 warps (64x32 each),
//   one barrier per 2 K-blocks, register-level fragment double-buffer.
//   Exact group-scale dual accumulators; scale_x[t] at the epilogue.
//   (At the legacy-HMMA pipe ceiling: ~1450 cyc/kb = 128 HMMA x rt 11.3.)
// ============================================================
#define BKB 128                 // bytes per smem row (64 bf16)
#define NSTG 6
#define STGB (128 * BKB)        // 16 KB per operand stage
#define NKB (I_DIM / 64)        // 64 k-blocks, 4 per group

__device__ __forceinline__ void cp_async16(uint32_t smem, const void* gmem) {
    asm volatile("cp.async.cg.shared.global [%0], [%1], 16;\n" :: "r"(smem), "l"(gmem));
}
__device__ __forceinline__ void cp_commit() { asm volatile("cp.async.commit_group;\n"); }
__device__ __forceinline__ void cp_wait2()  { asm volatile("cp.async.wait_group 2;\n"); }

__device__ __forceinline__ void ldmx4(unsigned& r0, unsigned& r1, unsigned& r2, unsigned& r3,
                                      uint32_t addr) {
    asm volatile("ldmatrix.sync.aligned.m8n8.x4.shared.b16 {%0,%1,%2,%3}, [%4];"
                 : "=r"(r0), "=r"(r1), "=r"(r2), "=r"(r3) : "r"(addr));
}

__global__ void __launch_bounds__(256, 1)
gemm_kernel(const float* __restrict__ scales, float* __restrict__ out) {
    extern __shared__ char smem_dyn[];
    uint32_t raw = (uint32_t)__cvta_generic_to_shared(smem_dyn);
    const uint32_t sA = (raw + 127u) & ~127u;            // 128B-aligned rows
    const uint32_t sB = sA + NSTG * STGB;
    float* s_sc = reinterpret_cast<float*>(smem_dyn + (sB + NSTG * STGB - raw));

    const int tid  = threadIdx.x;
    const int wid  = tid >> 5;
    const int lane = tid & 31;
    const int bm   = blockIdx.y * 128;
    const int bn   = blockIdx.x * 128;

    // warp grid 2(M) x 4(N); warp tile 64x32
    const int mbase = (wid & 1) * 64;
    const int nbase = (wid >> 1) * 32;
    const int q  = lane >> 3;          // ldmatrix address quad
    const int l7 = lane & 7;

    // --- producer indexing: each thread loads rows r0+32i (i=0..3), chunk j ---
    const int r0 = tid >> 3;           // 0..31
    const int j  = tid & 7;
    const uint32_t swoff = (uint32_t)((j ^ (r0 & 7)) << 4);
    const uint32_t dA0 = sA + r0 * BKB + swoff;   // rows r0+32i share (r&7)
    const uint32_t dB0 = sB + r0 * BKB + swoff;
    const char* Ar0 = (const char*)(g_A + (size_t)(bm + r0) * I_DIM) + j * 16;
    const char* Br0 = (const char*)(g_B + (size_t)(bn + r0) * I_DIM) + j * 16;
    const size_t rstep = (size_t)32 * I_DIM * 2;   // 32 rows of bf16

    // --- ldmatrix per-lane row constants ---
    uint32_t arow128[4], arow7[4], brow128[2], brow7[2];
#pragma unroll
    for (int mi = 0; mi < 4; ++mi) {
        int r = mbase + mi * 16 + (q & 1) * 8 + l7;
        arow128[mi] = (uint32_t)(r * BKB);
        arow7[mi]   = (uint32_t)(r & 7);
    }
#pragma unroll
    for (int p = 0; p < 2; ++p) {
        int r = nbase + p * 16 + (q >> 1) * 8 + l7;
        brow128[p] = (uint32_t)(r * BKB);
        brow7[p]   = (uint32_t)(r & 7);
    }
    const uint32_t aq = (uint32_t)(q >> 1);   // A k-chunk offset
    const uint32_t bq = (uint32_t)(q & 1);    // B k-chunk offset

    // --- stage scales: s_sc[g*128 + col] = scales[(bn+col)*16 + g] ---
    for (int i = tid; i < GROUPS * 128; i += 256) {
        int g = i >> 7, c = i & 127;
        s_sc[i] = __ldg(&scales[(size_t)(bn + c) * GROUPS + g]);
    }

    float accg[4][4][4], acct[4][4][4];
#pragma unroll
    for (int mi = 0; mi < 4; ++mi)
#pragma unroll
        for (int ni = 0; ni < 4; ++ni)
#pragma unroll
            for (int c = 0; c < 4; ++c) { accg[mi][ni][c] = 0.f; acct[mi][ni][c] = 0.f; }

    // --- prologue: prefetch kb = 0,1,2,3 into stages 0..3 (one commit each) ---
#pragma unroll
    for (int kb = 0; kb < 4; ++kb) {
        const uint32_t so = (uint32_t)kb * STGB;
        const size_t go = (size_t)kb * BKB;
#pragma unroll
        for (int i = 0; i < 4; ++i) {
            cp_async16(dA0 + so + i * 32 * BKB, Ar0 + go + i * rstep);
            cp_async16(dB0 + so + i * 32 * BKB, Br0 + go + i * rstep);
        }
        cp_commit();
    }

    // fragment double buffers
    unsigned fa[2][4][4], fb[2][4][2];

#define LDFRAG(buf, sAc, sBc, k16) do {                                         \
        _Pragma("unroll")                                                       \
        for (int mi = 0; mi < 4; ++mi) {                                        \
            uint32_t addr = (sAc) + arow128[mi] +                               \
                            ((((uint32_t)((k16) << 1) + aq) ^ arow7[mi]) << 4); \
            ldmx4(fa[buf][mi][0], fa[buf][mi][1], fa[buf][mi][2],               \
                  fa[buf][mi][3], addr);                                        \
        }                                                                       \
        _Pragma("unroll")                                                       \
        for (int p = 0; p < 2; ++p) {                                           \
            uint32_t addr = (sBc) + brow128[p] +                                \
                            ((((uint32_t)((k16) << 1) + bq) ^ brow7[p]) << 4);  \
            ldmx4(fb[buf][2 * p][0], fb[buf][2 * p][1],                         \
                  fb[buf][2 * p + 1][0], fb[buf][2 * p + 1][1], addr);          \
        }                                                                       \
    } while (0)

#define DOMMA(buf) do {                                                         \
        _Pragma("unroll")                                                       \
        for (int mi = 0; mi < 4; ++mi)                                          \
            _Pragma("unroll")                                                   \
            for (int ni = 0; ni < 4; ++ni) {                                    \
                float* c = accg[mi][ni];                                        \
                asm volatile(                                                   \
                    "mma.sync.aligned.m16n8k16.row.col.f32.bf16.bf16.f32 "      \
                    "{%0,%1,%2,%3},{%4,%5,%6,%7},{%8,%9},{%0,%1,%2,%3};\n"      \
                    : "+f"(c[0]), "+f"(c[1]), "+f"(c[2]), "+f"(c[3])            \
                    : "r"(fa[buf][mi][0]), "r"(fa[buf][mi][1]),                 \
                      "r"(fa[buf][mi][2]), "r"(fa[buf][mi][3]),                 \
                      "r"(fb[buf][ni][0]), "r"(fb[buf][ni][1]));                \
            }                                                                   \
    } while (0)

    int st = 0;   // stage of kb = 2*kb2 ; cycles 0,2,4
    for (int kb2 = 0; kb2 < NKB / 2; ++kb2) {
        // stages st, st+1 complete (own groups), publish cross-thread
        cp_wait2();
        __syncthreads();

        // --- prefetch the next two k-blocks immediately (overlaps compute) ---
        {
            const int pk0 = 2 * kb2 + 4;
            const int ps0 = (st + 4 >= NSTG) ? st + 4 - NSTG : st + 4;  // even
            if (pk0 < NKB) {
                const uint32_t so = (uint32_t)ps0 * STGB;
                const size_t go = (size_t)pk0 * BKB;
#pragma unroll
                for (int i = 0; i < 4; ++i) {
                    cp_async16(dA0 + so + i * 32 * BKB, Ar0 + go + i * rstep);
                    cp_async16(dB0 + so + i * 32 * BKB, Br0 + go + i * rstep);
                }
            }
            cp_commit();
            if (pk0 + 1 < NKB) {
                const uint32_t so = (uint32_t)(ps0 + 1) * STGB;
                const size_t go = (size_t)(pk0 + 1) * BKB;
#pragma unroll
                for (int i = 0; i < 4; ++i) {
                    cp_async16(dA0 + so + i * 32 * BKB, Ar0 + go + i * rstep);
                    cp_async16(dB0 + so + i * 32 * BKB, Br0 + go + i * rstep);
                }
            }
            cp_commit();
        }

        // --- compute 2 k-blocks (K=128): 8 k16 steps, frag double-buffered ---
        const uint32_t sAc0 = sA + (uint32_t)st * STGB;
        const uint32_t sBc0 = sB + (uint32_t)st * STGB;
        const uint32_t sAc1 = sAc0 + STGB;
        const uint32_t sBc1 = sBc0 + STGB;

        LDFRAG(0, sAc0, sBc0, 0);
#pragma unroll
        for (int s = 0; s < 8; ++s) {
            const int cb = s & 1;
            if (s < 7) {
                const int k2 = (s + 1) & 3;
                if (((s + 1) >> 2) == 0) { LDFRAG(!(s & 1) ? 1 : 0, sAc0, sBc0, k2); }
                else                     { LDFRAG(!(s & 1) ? 1 : 0, sAc1, sBc1, k2); }
            }
            DOMMA(cb);
        }

        // fold group scale every 256 K (4 kb): after odd kb2
        if (kb2 & 1) {
            const int g = kb2 >> 1;
            const float* sg = s_sc + g * 128;
#pragma unroll
            for (int ni = 0; ni < 4; ++ni) {
                const int c = nbase + ni * 8 + ((lane & 3) << 1);
                const float s0 = sg[c];
                const float s1 = sg[c + 1];
#pragma unroll
                for (int mi = 0; mi < 4; ++mi) {
                    acct[mi][ni][0] = fmaf(s0, accg[mi][ni][0], acct[mi][ni][0]);
                    acct[mi][ni][1] = fmaf(s1, accg[mi][ni][1], acct[mi][ni][1]);
                    acct[mi][ni][2] = fmaf(s0, accg[mi][ni][2], acct[mi][ni][2]);
                    acct[mi][ni][3] = fmaf(s1, accg[mi][ni][3], acct[mi][ni][3]);
                    accg[mi][ni][0] = 0.f; accg[mi][ni][1] = 0.f;
                    accg[mi][ni][2] = 0.f; accg[mi][ni][3] = 0.f;
                }
            }
        }

        st += 2;
        if (st == NSTG) st = 0;
    }

    // epilogue: out[t,o] = scale_x[t] * total
#pragma unroll
    for (int mi = 0; mi < 4; ++mi) {
        const int row0 = bm + mbase + mi * 16 + (lane >> 2);
        const int row1 = row0 + 8;
        const float sx0 = __ldg(&g_sx[row0]);
        const float sx1 = __ldg(&g_sx[row1]);
#pragma unroll
        for (int ni = 0; ni < 4; ++ni) {
            const int col = bn + nbase + ni * 8 + ((lane & 3) << 1);
            float2 v0 = make_float2(sx0 * acct[mi][ni][0], sx0 * acct[mi][ni][1]);
            float2 v1 = make_float2(sx1 * acct[mi][ni][2], sx1 * acct[mi][ni][3]);
            *reinterpret_cast<float2*>(out + (size_t)row0 * O_DIM + col) = v0;
            *reinterpret_cast<float2*>(out + (size_t)row1 * O_DIM + col) = v1;
        }
    }
}

#define SMEM_NEED (2 * NSTG * STGB + GROUPS * 128 * 4 + 256)

// ============================================================
extern "C" void kernel_launch(void* const* d_in, const int* in_sizes, int n_in,
                              void* d_out, int out_size) {
    const float* x      = (const float*)d_in[0];
    const int*   w      = (const int*)  d_in[1];
    const float* scales = (const float*)d_in[2];
    const float* zeros  = (const float*)d_in[3];
    float* out = (float*)d_out;

    cudaFuncSetAttribute(gemm_kernel, cudaFuncAttributeMaxDynamicSharedMemorySize, SMEM_NEED);

    prep_kernel<<<T_DIM + WPREP_BLOCKS, 256>>>(x, w, zeros);
    gemm_kernel<<<dim3(O_DIM / 128, T_DIM / 128), 256, SMEM_NEED>>>(scales, out);
}